// round 7
// baseline (speedup 1.0000x reference)
#include <cuda_runtime.h>
#include <cstdint>

#define HW 3136
#define EPS 1e-5f
#define NPATCH 3136   // 16 b * 4 g * 7 * 7

// Scratch (device globals: no runtime allocation allowed)
__device__ float g_mid1[16 * 128 * HW];
__device__ float g_mid2[16 * 128 * HW];
__device__ int g_acnt[4];          // active count per group
__device__ int g_ninact;
__device__ int g_lista[4 * 784];   // per-group active patch ids
__device__ int g_listi[NPATCH];    // inactive patch ids

// ---------------------------------------------------------------------------
// prep: bucket active patches by group; inactive into one list
// patch id i: b=i/196, g=(i/49)&3, pr=(i/7)%7, pc=i%7
// ---------------------------------------------------------------------------
__global__ void prep(const float* __restrict__ mask) {
    __shared__ int cnt[4];
    __shared__ int icnt;
    int t = threadIdx.x;
    if (t < 4) cnt[t] = 0;
    if (t == 0) icnt = 0;
    __syncthreads();
    for (int i = t; i < NPATCH; i += blockDim.x) {
        int g = (i / 49) & 3;
        if (mask[i] != 0.f) {
            int p = atomicAdd(&cnt[g], 1);
            g_lista[g * 784 + p] = i;
        } else {
            int p = atomicAdd(&icnt, 1);
            g_listi[p] = i;
        }
    }
    __syncthreads();
    if (t < 4) g_acnt[t] = cnt[t];
    if (t == 0) g_ninact = icnt;
}

// ---------------------------------------------------------------------------
// zero_inactive: zero mid1 only for inactive patches (k2 halo reads them)
// grid=448, 224 thr; warp w handles patch g_listi[blk*7+w]
// ---------------------------------------------------------------------------
__global__ __launch_bounds__(224) void zero_inactive() {
    const int t = threadIdx.x, blk = blockIdx.x;
    const int w = t >> 5, l = t & 31;
    const int s = blk * 7 + w;
    if (s >= g_ninact) return;
    const int packed = g_listi[s];
    const int pc = packed % 7;
    const int rest = packed / 7;
    const int pr = rest % 7;
    const int bgp = rest / 7;
    const int g = bgp & 3, b = bgp >> 2;
    const int r = l >> 2, cp = l & 3;
    float* op = g_mid1 + (size_t)(b * 128 + g * 32) * HW + (pr * 8 + r) * 56 + pc * 8 + cp * 2;
    float2 z = make_float2(0.f, 0.f);
#pragma unroll
    for (int j = 0; j < 32; j++) *(float2*)(op + (size_t)j * HW) = z;
}

// ---------------------------------------------------------------------------
// K1: 1x1 conv (128 -> 16 oc per block) + BN1 + ReLU + mask premult
// grid = 2 qc * 4 g * 112; block serves 7 active patches of ONE group
// ---------------------------------------------------------------------------
__global__ __launch_bounds__(224, 3) void k1(const float* __restrict__ x,
                                             const float* __restrict__ mask,
                                             const float* __restrict__ w1,
                                             const float* __restrict__ bg1,
                                             const float* __restrict__ bb1,
                                             const float* __restrict__ bm1,
                                             const float* __restrict__ bv1) {
    __shared__ __align__(16) float ws[2048];  // [128 ic][16 oc]

    const int t = threadIdx.x, blk = blockIdx.x;
    const int qc = blk & 1;
    const int bg = blk >> 1;
    const int g = bg / 112, ib = bg % 112;
    const int nact = g_acnt[g];
    if (ib * 7 >= nact) return;

    for (int e = t; e < 2048; e += 224) {
        int j = e >> 7, ic = e & 127;
        ws[ic * 16 + j] = w1[(g * 32 + qc * 16 + j) * 128 + ic];
    }
    __syncthreads();

    const int w = t >> 5, l = t & 31;
    const int idx = ib * 7 + w;
    if (idx >= nact) return;
    const int packed = g_lista[g * 784 + idx];
    const int pc = packed % 7;
    const int pr = (packed / 7) % 7;
    const int b = packed / 196;
    const float m = mask[packed];

    const int r = l >> 2, cp = l & 3;
    const int grow = pr * 8 + r;
    const int col = pc * 8 + cp * 2;

    const float* xp = x + (size_t)(b * 512 + g * 128) * HW + grow * 56 + col;
    float* op = g_mid1 + (size_t)(b * 128 + g * 32 + qc * 16) * HW + grow * 56 + col;

    float a0[16], a1[16];
#pragma unroll
    for (int j = 0; j < 16; j++) { a0[j] = 0.f; a1[j] = 0.f; }

    for (int ic0 = 0; ic0 < 128; ic0 += 8) {
        float2 xv[8];
#pragma unroll
        for (int u = 0; u < 8; u++)
            xv[u] = *(const float2*)(xp + (size_t)(ic0 + u) * HW);
#pragma unroll
        for (int u = 0; u < 8; u++) {
            const float4* wp = (const float4*)(ws + (ic0 + u) * 16);
#pragma unroll
            for (int j = 0; j < 4; j++) {
                float4 q = wp[j];
                a0[4 * j + 0] = fmaf(xv[u].x, q.x, a0[4 * j + 0]);
                a0[4 * j + 1] = fmaf(xv[u].x, q.y, a0[4 * j + 1]);
                a0[4 * j + 2] = fmaf(xv[u].x, q.z, a0[4 * j + 2]);
                a0[4 * j + 3] = fmaf(xv[u].x, q.w, a0[4 * j + 3]);
                a1[4 * j + 0] = fmaf(xv[u].y, q.x, a1[4 * j + 0]);
                a1[4 * j + 1] = fmaf(xv[u].y, q.y, a1[4 * j + 1]);
                a1[4 * j + 2] = fmaf(xv[u].y, q.z, a1[4 * j + 2]);
                a1[4 * j + 3] = fmaf(xv[u].y, q.w, a1[4 * j + 3]);
            }
        }
    }
#pragma unroll
    for (int j = 0; j < 16; j++) {
        int c = g * 32 + qc * 16 + j;
        float s = bg1[c] * rsqrtf(bv1[c] + EPS);
        float bb = bb1[c] - bm1[c] * s;
        float v0 = fmaxf(fmaf(m * a0[j], s, bb), 0.f) * m;
        float v1 = fmaxf(fmaf(m * a1[j], s, bb), 0.f) * m;
        *(float2*)(op + (size_t)j * HW) = make_float2(v0, v1);
    }
}

// ---------------------------------------------------------------------------
// K2: 3x3 conv (32 -> 16 oc per block) + BN2 + ReLU + mask
// Per-warp smem halo tile: 10x10x(8 ic chunk), loaded coalesced, taps via LDS.
// grid = 2 qc * 4 g * 112
// ---------------------------------------------------------------------------
__global__ __launch_bounds__(224, 3) void k2(const float* __restrict__ mask,
                                             const float* __restrict__ w2,
                                             const float* __restrict__ bg2,
                                             const float* __restrict__ bb2,
                                             const float* __restrict__ bm2,
                                             const float* __restrict__ bv2) {
    __shared__ __align__(16) float ws[4608];       // [32 ic][9][16 oc]
    __shared__ __align__(16) float s_tile[6720];   // 7 warps x [8 ic][10][12]

    const int t = threadIdx.x, blk = blockIdx.x;
    const int qc = blk & 1;
    const int bg = blk >> 1;
    const int g = bg / 112, ib = bg % 112;
    const int nact = g_acnt[g];
    if (ib * 7 >= nact) return;

    for (int e = t; e < 4608; e += 224) {
        int j = e / 288;
        int rem = e - j * 288;
        int ic = rem / 9;
        int kk = rem - ic * 9;
        ws[(ic * 9 + kk) * 16 + j] = w2[((g * 32 + qc * 16 + j) * 32 + ic) * 9 + kk];
    }
    __syncthreads();

    const int w = t >> 5, l = t & 31;
    const int idx = ib * 7 + w;
    if (idx >= nact) return;
    const int packed = g_lista[g * 784 + idx];
    const int pc = packed % 7;
    const int pr = (packed / 7) % 7;
    const int b = packed / 196;
    const float m = mask[packed];

    const int r = l >> 2, cp = l & 3;
    const int grow0 = pr * 8, col0 = pc * 8;

    const float* mb = g_mid1 + (size_t)(b * 128 + g * 32) * HW;
    float* op = g_mid2 + (size_t)(b * 128 + g * 32 + qc * 16) * HW + (grow0 + r) * 56 + col0 + cp * 2;
    float* tile = s_tile + w * 960;

    float a0[16], a1[16];
#pragma unroll
    for (int j = 0; j < 16; j++) { a0[j] = 0.f; a1[j] = 0.f; }

    for (int ic0 = 0; ic0 < 32; ic0 += 8) {
        __syncwarp();
        // load 8 ic x 10 x 10 halo region (800 elems = 25 per lane)
#pragma unroll
        for (int k = 0; k < 25; k++) {
            int e = l + k * 32;
            int ic_off = e / 100;
            int rem = e - ic_off * 100;
            int ry = rem / 10;
            int cx = rem - ry * 10;
            int gy = grow0 - 1 + ry;
            int gx = col0 - 1 + cx;
            float v = 0.f;
            if (gy >= 0 && gy < 56 && gx >= 0 && gx < 56)
                v = mb[(size_t)(ic0 + ic_off) * HW + gy * 56 + gx];
            tile[ic_off * 120 + ry * 12 + cx] = v;
        }
        __syncwarp();

#pragma unroll
        for (int ic_off = 0; ic_off < 8; ic_off++) {
            const float* trow = tile + ic_off * 120 + r * 12 + 2 * cp;
#pragma unroll
            for (int dy = 0; dy < 3; dy++) {
                float2 u = *(const float2*)(trow + dy * 12);
                float2 v = *(const float2*)(trow + dy * 12 + 2);
                float t0 = u.x, t1 = u.y, t2 = v.x, t3 = v.y;
                const float4* wp = (const float4*)(ws + ((ic0 + ic_off) * 9 + dy * 3) * 16);
#pragma unroll
                for (int j = 0; j < 4; j++) {
                    float4 wa = wp[j];
                    float4 wb = wp[4 + j];
                    float4 wc = wp[8 + j];
                    a0[4 * j + 0] = fmaf(t0, wa.x, fmaf(t1, wb.x, fmaf(t2, wc.x, a0[4 * j + 0])));
                    a0[4 * j + 1] = fmaf(t0, wa.y, fmaf(t1, wb.y, fmaf(t2, wc.y, a0[4 * j + 1])));
                    a0[4 * j + 2] = fmaf(t0, wa.z, fmaf(t1, wb.z, fmaf(t2, wc.z, a0[4 * j + 2])));
                    a0[4 * j + 3] = fmaf(t0, wa.w, fmaf(t1, wb.w, fmaf(t2, wc.w, a0[4 * j + 3])));
                    a1[4 * j + 0] = fmaf(t1, wa.x, fmaf(t2, wb.x, fmaf(t3, wc.x, a1[4 * j + 0])));
                    a1[4 * j + 1] = fmaf(t1, wa.y, fmaf(t2, wb.y, fmaf(t3, wc.y, a1[4 * j + 1])));
                    a1[4 * j + 2] = fmaf(t1, wa.z, fmaf(t2, wb.z, fmaf(t3, wc.z, a1[4 * j + 2])));
                    a1[4 * j + 3] = fmaf(t1, wa.w, fmaf(t2, wb.w, fmaf(t3, wc.w, a1[4 * j + 3])));
                }
            }
        }
    }
#pragma unroll
    for (int j = 0; j < 16; j++) {
        int c = g * 32 + qc * 16 + j;
        float s = bg2[c] * rsqrtf(bv2[c] + EPS);
        float bb = bb2[c] - bm2[c] * s;
        float v0 = fmaxf(fmaf(a0[j], s, bb), 0.f) * m;
        float v1 = fmaxf(fmaf(a1[j], s, bb), 0.f) * m;
        *(float2*)(op + (size_t)j * HW) = make_float2(v0, v1);
    }
}

// ---------------------------------------------------------------------------
// K3: 1x1 conv (32 -> 16 oc per block) + BN3 + residual + ReLU, all patches
// grid = 448 patch-blocks * 8 qc; warp slot s -> bucketed actives then inactives
// ---------------------------------------------------------------------------
__global__ __launch_bounds__(224, 3) void k3(const float* __restrict__ x,
                                             const float* __restrict__ mask,
                                             const float* __restrict__ w3,
                                             const float* __restrict__ bg3,
                                             const float* __restrict__ bb3,
                                             const float* __restrict__ bm3,
                                             const float* __restrict__ bv3,
                                             float* __restrict__ out) {
    __shared__ __align__(16) float ws[2048];  // [4 g][32 ic][16 oc]

    const int t = threadIdx.x, blk = blockIdx.x;
    const int qc = blk & 7;
    const int pb = blk >> 3;

    for (int e = t; e < 2048; e += 224) {
        int gg = e >> 9;
        int rem = e & 511;
        int j = rem >> 5, ic = rem & 31;
        ws[gg * 512 + ic * 16 + j] = w3[(gg * 128 + qc * 16 + j) * 32 + ic];
    }
    __syncthreads();

    const int w = t >> 5, l = t & 31;
    const int s = pb * 7 + w;  // 0..3135
    int c0 = g_acnt[0], c1 = g_acnt[1], c2 = g_acnt[2], c3 = g_acnt[3];
    int t0 = c0, t1 = t0 + c1, t2 = t1 + c2, t3 = t2 + c3;
    int packed;
    bool active = (s < t3);
    if (s < t0)      packed = g_lista[s];
    else if (s < t1) packed = g_lista[784 + s - t0];
    else if (s < t2) packed = g_lista[1568 + s - t1];
    else if (s < t3) packed = g_lista[2352 + s - t2];
    else             packed = g_listi[s - t3];

    const int pc = packed % 7;
    const int rest = packed / 7;
    const int pr = rest % 7;
    const int bgp = rest / 7;
    const int g = bgp & 3, b = bgp >> 2;

    const int r = l >> 2, cp = l & 3;
    const int grow = pr * 8 + r;
    const int col = pc * 8 + cp * 2;

    const float* resp = x + (size_t)(b * 512 + g * 128 + qc * 16) * HW + grow * 56 + col;
    float* op = out + (size_t)(b * 512 + g * 128 + qc * 16) * HW + grow * 56 + col;

    float sc[16], bi[16];
#pragma unroll
    for (int j = 0; j < 16; j++) {
        int c = g * 128 + qc * 16 + j;
        float ss = bg3[c] * rsqrtf(bv3[c] + EPS);
        sc[j] = ss;
        bi[j] = bb3[c] - bm3[c] * ss;
    }

    if (active) {
        const float m = mask[packed];
        const float* mp = g_mid2 + (size_t)(b * 128 + g * 32) * HW + grow * 56 + col;
        const float* wsg = ws + g * 512;
        float a0[16], a1[16];
#pragma unroll
        for (int j = 0; j < 16; j++) { a0[j] = 0.f; a1[j] = 0.f; }

        for (int ic0 = 0; ic0 < 32; ic0 += 8) {
            float2 xv[8];
#pragma unroll
            for (int u = 0; u < 8; u++)
                xv[u] = *(const float2*)(mp + (size_t)(ic0 + u) * HW);
#pragma unroll
            for (int u = 0; u < 8; u++) {
                const float4* wp = (const float4*)(wsg + (ic0 + u) * 16);
#pragma unroll
                for (int j = 0; j < 4; j++) {
                    float4 q = wp[j];
                    a0[4 * j + 0] = fmaf(xv[u].x, q.x, a0[4 * j + 0]);
                    a0[4 * j + 1] = fmaf(xv[u].x, q.y, a0[4 * j + 1]);
                    a0[4 * j + 2] = fmaf(xv[u].x, q.z, a0[4 * j + 2]);
                    a0[4 * j + 3] = fmaf(xv[u].x, q.w, a0[4 * j + 3]);
                    a1[4 * j + 0] = fmaf(xv[u].y, q.x, a1[4 * j + 0]);
                    a1[4 * j + 1] = fmaf(xv[u].y, q.y, a1[4 * j + 1]);
                    a1[4 * j + 2] = fmaf(xv[u].y, q.z, a1[4 * j + 2]);
                    a1[4 * j + 3] = fmaf(xv[u].y, q.w, a1[4 * j + 3]);
                }
            }
        }
        // NOTE: conv3 input already mask-premultiplied in k2 epilogue; m only
        // appears there, residual path exact.
        (void)m;
#pragma unroll
        for (int j = 0; j < 16; j++) {
            float2 res = *(const float2*)(resp + (size_t)j * HW);
            float v0 = fmaxf(fmaf(a0[j], sc[j], bi[j]) + res.x, 0.f);
            float v1 = fmaxf(fmaf(a1[j], sc[j], bi[j]) + res.y, 0.f);
            *(float2*)(op + (size_t)j * HW) = make_float2(v0, v1);
        }
    } else {
#pragma unroll
        for (int j = 0; j < 16; j++) {
            float2 res = *(const float2*)(resp + (size_t)j * HW);
            float v0 = fmaxf(bi[j] + res.x, 0.f);
            float v1 = fmaxf(bi[j] + res.y, 0.f);
            *(float2*)(op + (size_t)j * HW) = make_float2(v0, v1);
        }
    }
}

// ---------------------------------------------------------------------------
extern "C" void kernel_launch(void* const* d_in, const int* in_sizes, int n_in,
                              void* d_out, int out_size) {
    const float* x    = (const float*)d_in[0];
    const float* mask = (const float*)d_in[1];
    const float* w1   = (const float*)d_in[2];
    const float* g1 = (const float*)d_in[3];
    const float* b1 = (const float*)d_in[4];
    const float* m1 = (const float*)d_in[5];
    const float* v1 = (const float*)d_in[6];
    const float* w2   = (const float*)d_in[7];
    const float* g2 = (const float*)d_in[8];
    const float* b2 = (const float*)d_in[9];
    const float* m2 = (const float*)d_in[10];
    const float* v2 = (const float*)d_in[11];
    const float* w3   = (const float*)d_in[12];
    const float* g3 = (const float*)d_in[13];
    const float* b3 = (const float*)d_in[14];
    const float* m3 = (const float*)d_in[15];
    const float* v3 = (const float*)d_in[16];
    float* out = (float*)d_out;

    prep<<<1, 1024>>>(mask);
    zero_inactive<<<448, 224>>>();

    k1<<<2 * 4 * 112, 224>>>(x, mask, w1, g1, b1, m1, v1);
    k2<<<2 * 4 * 112, 224>>>(mask, w2, g2, b2, m2, v2);
    k3<<<448 * 8, 224>>>(x, mask, w3, g3, b3, m3, v3, out);
}

// round 9
// speedup vs baseline: 1.2574x; 1.2574x over previous
#include <cuda_runtime.h>
#include <cstdint>

#define HW 3136
#define EPS 1e-5f

// Scratch (device globals: no runtime allocation allowed)
__device__ float g_mid1[16 * 128 * HW];
__device__ float g_mid2[16 * 128 * HW];

// ---- packed f32x2 helpers (sm_103a) ----
__device__ __forceinline__ unsigned long long pk2(float a, float b) {
    unsigned long long r;
    asm("mov.b64 %0, {%1, %2};" : "=l"(r) : "f"(a), "f"(b));
    return r;
}
__device__ __forceinline__ void fma2(unsigned long long& d, unsigned long long a,
                                     unsigned long long b) {
    asm("fma.rn.f32x2 %0, %1, %2, %0;" : "+l"(d) : "l"(a), "l"(b));
}
__device__ __forceinline__ float2 upk2(unsigned long long v) {
    float2 r;
    asm("mov.b64 {%0, %1}, %2;" : "=f"(r.x), "=f"(r.y) : "l"(v));
    return r;
}

// Common decode: 224 threads = 7 warps; warp = patch column, lane: r=l>>2 row,
// cp=l&3 col-pair; thread owns 2 adjacent pixels. Mask is warp-uniform.
// Accumulators packed over oc PAIRS: A0[p] = (acc[2p], acc[2p+1]) for pixel0.

// ---------------------------------------------------------------------------
// K1: 1x1 conv (128 -> 8 oc per block) + BN1 + ReLU + mask premult
// grid = (b, g, pr, qc in 0..3)
// ---------------------------------------------------------------------------
__global__ __launch_bounds__(224, 5) void k1(const float* __restrict__ x,
                                             const float* __restrict__ mask,
                                             const float* __restrict__ w1,
                                             const float* __restrict__ bg1,
                                             const float* __restrict__ bb1,
                                             const float* __restrict__ bm1,
                                             const float* __restrict__ bv1) {
    __shared__ __align__(16) float ws[1024];  // [ic][8]

    const int t = threadIdx.x, blk = blockIdx.x;
    const int qc = blk & 3;
    const int rest = blk >> 2;
    const int pr = rest % 7;
    const int bg = rest / 7;
    const int g = bg & 3, b = bg >> 2;

    for (int e = t; e < 1024; e += 224) {
        int j = e >> 7, ic = e & 127;
        ws[ic * 8 + j] = w1[(g * 32 + qc * 8 + j) * 128 + ic];
    }
    __syncthreads();

    const int w = t >> 5, l = t & 31;
    const int r = l >> 2, cp = l & 3;
    const int grow = pr * 8 + r;
    const int col = w * 8 + cp * 2;
    const float m = mask[((b * 4 + g) * 7 + pr) * 7 + w];

    float* op = g_mid1 + (size_t)(b * 128 + g * 32 + qc * 8) * HW + grow * 56 + col;

    if (m != 0.f) {
        const float* xp = x + (size_t)(b * 512 + g * 128) * HW + grow * 56 + col;
        unsigned long long A0[4], A1[4];
#pragma unroll
        for (int j = 0; j < 4; j++) { A0[j] = 0ull; A1[j] = 0ull; }

        for (int ic0 = 0; ic0 < 128; ic0 += 8) {
            float2 xv[8];
#pragma unroll
            for (int u = 0; u < 8; u++)
                xv[u] = *(const float2*)(xp + (size_t)(ic0 + u) * HW);
#pragma unroll
            for (int u = 0; u < 8; u++) {
                const ulonglong2* wp = (const ulonglong2*)(ws + (ic0 + u) * 8);
                ulonglong2 q0 = wp[0];  // oc pairs 0,1
                ulonglong2 q1 = wp[1];  // oc pairs 2,3
                unsigned long long xx0 = pk2(xv[u].x, xv[u].x);
                unsigned long long xx1 = pk2(xv[u].y, xv[u].y);
                fma2(A0[0], xx0, q0.x); fma2(A0[1], xx0, q0.y);
                fma2(A0[2], xx0, q1.x); fma2(A0[3], xx0, q1.y);
                fma2(A1[0], xx1, q0.x); fma2(A1[1], xx1, q0.y);
                fma2(A1[2], xx1, q1.x); fma2(A1[3], xx1, q1.y);
            }
        }
#pragma unroll
        for (int p = 0; p < 4; p++) {
            float2 u0 = upk2(A0[p]);
            float2 u1 = upk2(A1[p]);
            float a0[2] = {u0.x, u0.y}, a1[2] = {u1.x, u1.y};
#pragma unroll
            for (int jj = 0; jj < 2; jj++) {
                int j = p * 2 + jj;
                int c = g * 32 + qc * 8 + j;
                float s = bg1[c] * rsqrtf(bv1[c] + EPS);
                float bb = bb1[c] - bm1[c] * s;
                float v0 = fmaxf(fmaf(m * a0[jj], s, bb), 0.f) * m;
                float v1 = fmaxf(fmaf(m * a1[jj], s, bb), 0.f) * m;
                *(float2*)(op + (size_t)j * HW) = make_float2(v0, v1);
            }
        }
    } else {
        float2 z = make_float2(0.f, 0.f);
#pragma unroll
        for (int j = 0; j < 8; j++) *(float2*)(op + (size_t)j * HW) = z;
    }
}

// ---------------------------------------------------------------------------
// K2: 3x3 conv (32 -> 8 oc per block, pad 1) + BN2 + ReLU + mask
// grid = (b, g, pr, qc in 0..3)
// smem weight layout: [ic][tap k][8 oc]; tap k spans flat u64 slots [4k, 4k+4)
// ---------------------------------------------------------------------------
__global__ __launch_bounds__(224, 4) void k2(const float* __restrict__ mask,
                                             const float* __restrict__ w2,
                                             const float* __restrict__ bg2,
                                             const float* __restrict__ bb2,
                                             const float* __restrict__ bm2,
                                             const float* __restrict__ bv2) {
    __shared__ __align__(16) float ws[2304];  // [ic][9][8]

    const int t = threadIdx.x, blk = blockIdx.x;
    const int qc = blk & 3;
    const int rest = blk >> 2;
    const int pr = rest % 7;
    const int bg = rest / 7;
    const int g = bg & 3, b = bg >> 2;

    for (int e = t; e < 2304; e += 224) {
        int j = e / 288;
        int rem = e - j * 288;
        int ic = rem / 9;
        int k = rem - ic * 9;
        ws[(ic * 9 + k) * 8 + j] = w2[((g * 32 + qc * 8 + j) * 32 + ic) * 9 + k];
    }
    __syncthreads();

    const int w = t >> 5, l = t & 31;
    const int r = l >> 2, cp = l & 3;
    const int grow = pr * 8 + r;
    const int col = w * 8 + cp * 2;
    const float m = mask[((b * 4 + g) * 7 + pr) * 7 + w];

    float* op = g_mid2 + (size_t)(b * 128 + g * 32 + qc * 8) * HW + grow * 56 + col;

    if (m != 0.f) {
        const float* mb = g_mid1 + (size_t)(b * 128 + g * 32) * HW + col;
        unsigned long long A0[4], A1[4];
#pragma unroll
        for (int j = 0; j < 4; j++) { A0[j] = 0ull; A1[j] = 0ull; }

#pragma unroll 2
        for (int ic = 0; ic < 32; ic++) {
            const float* pic = mb + (size_t)ic * HW;
            float xm[3], x2[3];
            float2 xc[3];
#pragma unroll
            for (int dy = 0; dy < 3; dy++) {
                int yy = grow - 1 + dy;
                bool v = (yy >= 0) && (yy < 56);
                const float* p = pic + yy * 56;
                xm[dy] = (v && col > 0) ? p[-1] : 0.f;
                xc[dy] = v ? *(const float2*)p : make_float2(0.f, 0.f);
                x2[dy] = (v && col < 54) ? p[2] : 0.f;
            }
#pragma unroll
            for (int dy = 0; dy < 3; dy++) {
                // row base for this (ic, dy): 3 taps x 8 oc = 24 floats = 6 u2
                const ulonglong2* wp = (const ulonglong2*)(ws + (ic * 9 + dy * 3) * 8);
                ulonglong2 ta = wp[0];   // tap dx=0, oc pairs 0,1
                ulonglong2 tA = wp[1];   // tap dx=0, oc pairs 2,3
                ulonglong2 tb = wp[2];   // tap dx=1, oc pairs 0,1
                ulonglong2 tB = wp[3];   // tap dx=1, oc pairs 2,3
                ulonglong2 tc = wp[4];   // tap dx=2, oc pairs 0,1
                ulonglong2 tC = wp[5];   // tap dx=2, oc pairs 2,3
                unsigned long long t00 = pk2(xm[dy], xm[dy]);
                unsigned long long t11 = pk2(xc[dy].x, xc[dy].x);
                unsigned long long t22 = pk2(xc[dy].y, xc[dy].y);
                unsigned long long t33 = pk2(x2[dy], x2[dy]);
                // pixel0 taps: (xm, xc.x, xc.y); pixel1 taps: (xc.x, xc.y, x2)
                fma2(A0[0], t00, ta.x); fma2(A0[1], t00, ta.y);
                fma2(A0[2], t00, tA.x); fma2(A0[3], t00, tA.y);
                fma2(A0[0], t11, tb.x); fma2(A0[1], t11, tb.y);
                fma2(A0[2], t11, tB.x); fma2(A0[3], t11, tB.y);
                fma2(A0[0], t22, tc.x); fma2(A0[1], t22, tc.y);
                fma2(A0[2], t22, tC.x); fma2(A0[3], t22, tC.y);
                fma2(A1[0], t11, ta.x); fma2(A1[1], t11, ta.y);
                fma2(A1[2], t11, tA.x); fma2(A1[3], t11, tA.y);
                fma2(A1[0], t22, tb.x); fma2(A1[1], t22, tb.y);
                fma2(A1[2], t22, tB.x); fma2(A1[3], t22, tB.y);
                fma2(A1[0], t33, tc.x); fma2(A1[1], t33, tc.y);
                fma2(A1[2], t33, tC.x); fma2(A1[3], t33, tC.y);
            }
        }
#pragma unroll
        for (int p = 0; p < 4; p++) {
            float2 u0 = upk2(A0[p]);
            float2 u1 = upk2(A1[p]);
            float a0[2] = {u0.x, u0.y}, a1[2] = {u1.x, u1.y};
#pragma unroll
            for (int jj = 0; jj < 2; jj++) {
                int j = p * 2 + jj;
                int c = g * 32 + qc * 8 + j;
                float s = bg2[c] * rsqrtf(bv2[c] + EPS);
                float bb = bb2[c] - bm2[c] * s;
                float v0 = fmaxf(fmaf(a0[jj], s, bb), 0.f) * m;
                float v1 = fmaxf(fmaf(a1[jj], s, bb), 0.f) * m;
                *(float2*)(op + (size_t)j * HW) = make_float2(v0, v1);
            }
        }
    } else {
        float2 z = make_float2(0.f, 0.f);
#pragma unroll
        for (int j = 0; j < 8; j++) *(float2*)(op + (size_t)j * HW) = z;
    }
}

// ---------------------------------------------------------------------------
// K3: 1x1 conv (32 -> 8 oc per block) + BN3 + residual + ReLU
// grid = (b, g, pr, qc in 0..15)
// ---------------------------------------------------------------------------
__global__ __launch_bounds__(224, 5) void k3(const float* __restrict__ x,
                                             const float* __restrict__ mask,
                                             const float* __restrict__ w3,
                                             const float* __restrict__ bg3,
                                             const float* __restrict__ bb3,
                                             const float* __restrict__ bm3,
                                             const float* __restrict__ bv3,
                                             float* __restrict__ out) {
    __shared__ __align__(16) float ws[256];  // [ic][8]

    const int t = threadIdx.x, blk = blockIdx.x;
    const int qc = blk & 15;
    const int rest = blk >> 4;
    const int pr = rest % 7;
    const int bg = rest / 7;
    const int g = bg & 3, b = bg >> 2;

    for (int e = t; e < 256; e += 224) {
        int j = e >> 5, ic = e & 31;
        ws[ic * 8 + j] = w3[(g * 128 + qc * 8 + j) * 32 + ic];
    }
    __syncthreads();

    const int w = t >> 5, l = t & 31;
    const int r = l >> 2, cp = l & 3;
    const int grow = pr * 8 + r;
    const int col = w * 8 + cp * 2;
    const float m = mask[((b * 4 + g) * 7 + pr) * 7 + w];

    const float* resp = x + (size_t)(b * 512 + g * 128 + qc * 8) * HW + grow * 56 + col;
    float* op = out + (size_t)(b * 512 + g * 128 + qc * 8) * HW + grow * 56 + col;

    float sc[8], bi[8];
#pragma unroll
    for (int j = 0; j < 8; j++) {
        int c = g * 128 + qc * 8 + j;
        float s = bg3[c] * rsqrtf(bv3[c] + EPS);
        sc[j] = s;
        bi[j] = bb3[c] - bm3[c] * s;
    }

    if (m != 0.f) {
        const float* mp = g_mid2 + (size_t)(b * 128 + g * 32) * HW + grow * 56 + col;
        unsigned long long A0[4], A1[4];
#pragma unroll
        for (int j = 0; j < 4; j++) { A0[j] = 0ull; A1[j] = 0ull; }

        for (int ic0 = 0; ic0 < 32; ic0 += 8) {
            float2 xv[8];
#pragma unroll
            for (int u = 0; u < 8; u++)
                xv[u] = *(const float2*)(mp + (size_t)(ic0 + u) * HW);
#pragma unroll
            for (int u = 0; u < 8; u++) {
                const ulonglong2* wp = (const ulonglong2*)(ws + (ic0 + u) * 8);
                ulonglong2 q0 = wp[0];
                ulonglong2 q1 = wp[1];
                unsigned long long xx0 = pk2(xv[u].x, xv[u].x);
                unsigned long long xx1 = pk2(xv[u].y, xv[u].y);
                fma2(A0[0], xx0, q0.x); fma2(A0[1], xx0, q0.y);
                fma2(A0[2], xx0, q1.x); fma2(A0[3], xx0, q1.y);
                fma2(A1[0], xx1, q0.x); fma2(A1[1], xx1, q0.y);
                fma2(A1[2], xx1, q1.x); fma2(A1[3], xx1, q1.y);
            }
        }
#pragma unroll
        for (int p = 0; p < 4; p++) {
            float2 u0 = upk2(A0[p]);
            float2 u1 = upk2(A1[p]);
            float a0[2] = {u0.x, u0.y}, a1[2] = {u1.x, u1.y};
#pragma unroll
            for (int jj = 0; jj < 2; jj++) {
                int j = p * 2 + jj;
                float2 res = *(const float2*)(resp + (size_t)j * HW);
                float v0 = fmaxf(fmaf(a0[jj], sc[j], bi[j]) + res.x, 0.f);
                float v1 = fmaxf(fmaf(a1[jj], sc[j], bi[j]) + res.y, 0.f);
                *(float2*)(op + (size_t)j * HW) = make_float2(v0, v1);
            }
        }
    } else {
#pragma unroll
        for (int j = 0; j < 8; j++) {
            float2 res = *(const float2*)(resp + (size_t)j * HW);
            float v0 = fmaxf(bi[j] + res.x, 0.f);
            float v1 = fmaxf(bi[j] + res.y, 0.f);
            *(float2*)(op + (size_t)j * HW) = make_float2(v0, v1);
        }
    }
}

// ---------------------------------------------------------------------------
extern "C" void kernel_launch(void* const* d_in, const int* in_sizes, int n_in,
                              void* d_out, int out_size) {
    const float* x    = (const float*)d_in[0];
    const float* mask = (const float*)d_in[1];
    const float* w1   = (const float*)d_in[2];
    const float* g1 = (const float*)d_in[3];
    const float* b1 = (const float*)d_in[4];
    const float* m1 = (const float*)d_in[5];
    const float* v1 = (const float*)d_in[6];
    const float* w2   = (const float*)d_in[7];
    const float* g2 = (const float*)d_in[8];
    const float* b2 = (const float*)d_in[9];
    const float* m2 = (const float*)d_in[10];
    const float* v2 = (const float*)d_in[11];
    const float* w3   = (const float*)d_in[12];
    const float* g3 = (const float*)d_in[13];
    const float* b3 = (const float*)d_in[14];
    const float* m3 = (const float*)d_in[15];
    const float* v3 = (const float*)d_in[16];
    float* out = (float*)d_out;

    k1<<<16 * 4 * 7 * 4, 224>>>(x, mask, w1, g1, b1, m1, v1);
    k2<<<16 * 4 * 7 * 4, 224>>>(mask, w2, g2, b2, m2, v2);
    k3<<<16 * 4 * 7 * 16, 224>>>(x, mask, w3, g3, b3, m3, v3, out);
}

// round 10
// speedup vs baseline: 1.2664x; 1.0071x over previous
#include <cuda_runtime.h>
#include <cstdint>

#define HW 3136
#define EPS 1e-5f
#define NPATCH 3136   // 16 b * 4 g * 7 * 7

// Scratch (device globals: no runtime allocation allowed)
__device__ float g_mid1[16 * 128 * HW];
__device__ float g_mid2[16 * 128 * HW];
__device__ int g_acnt[4];          // active count per group
__device__ int g_ninact;
__device__ int g_lista[4 * 784];   // per-group active patch ids
__device__ int g_listi[NPATCH];    // inactive patch ids

// ---- packed f32x2 helpers (sm_103a) ----
__device__ __forceinline__ unsigned long long pk2(float a, float b) {
    unsigned long long r;
    asm("mov.b64 %0, {%1, %2};" : "=l"(r) : "f"(a), "f"(b));
    return r;
}
__device__ __forceinline__ void fma2(unsigned long long& d, unsigned long long a,
                                     unsigned long long b) {
    asm("fma.rn.f32x2 %0, %1, %2, %0;" : "+l"(d) : "l"(a), "l"(b));
}
__device__ __forceinline__ float2 upk2(unsigned long long v) {
    float2 r;
    asm("mov.b64 {%0, %1}, %2;" : "=f"(r.x), "=f"(r.y) : "l"(v));
    return r;
}

// ---------------------------------------------------------------------------
// prep: bucket active patches by group; inactives into one list
// patch id i = b*196 + g*49 + pr*7 + pc
// ---------------------------------------------------------------------------
__global__ void prep(const float* __restrict__ mask) {
    __shared__ int cnt[4];
    __shared__ int icnt;
    int t = threadIdx.x;
    if (t < 4) cnt[t] = 0;
    if (t == 0) icnt = 0;
    __syncthreads();
    for (int i = t; i < NPATCH; i += blockDim.x) {
        int g = (i / 49) & 3;
        if (mask[i] != 0.f) {
            int p = atomicAdd(&cnt[g], 1);
            g_lista[g * 784 + p] = i;
        } else {
            int p = atomicAdd(&icnt, 1);
            g_listi[p] = i;
        }
    }
    __syncthreads();
    if (t < 4) g_acnt[t] = cnt[t];
    if (t == 0) g_ninact = icnt;
}

// ---------------------------------------------------------------------------
// zero_inactive: zero mid1 for inactive patches only (k2 halo reads them)
// ---------------------------------------------------------------------------
__global__ __launch_bounds__(224) void zero_inactive() {
    const int t = threadIdx.x, blk = blockIdx.x;
    const int w = t >> 5, l = t & 31;
    const int s = blk * 7 + w;
    if (s >= g_ninact) return;
    const int packed = g_listi[s];
    const int pc = packed % 7;
    const int pr = (packed / 7) % 7;
    const int g = (packed / 49) & 3;
    const int b = packed / 196;
    const int r = l >> 2, cp = l & 3;
    float* op = g_mid1 + (size_t)(b * 128 + g * 32) * HW + (pr * 8 + r) * 56 + pc * 8 + cp * 2;
    float2 z = make_float2(0.f, 0.f);
#pragma unroll
    for (int j = 0; j < 32; j++) *(float2*)(op + (size_t)j * HW) = z;
}

// Common decode: 224 threads = 7 warps; warp takes an ACTIVE patch from its
// group's list. lane: r=l>>2 row, cp=l&3 col-pair; thread owns 2 pixels.
// Accumulators packed over oc PAIRS (f32x2).

// ---------------------------------------------------------------------------
// K1: 1x1 conv (128 -> 8 oc per block) + BN1 + ReLU + mask premult
// grid = 4 qc * 4 g * 112 pb; active patches of one group only
// ---------------------------------------------------------------------------
__global__ __launch_bounds__(224, 5) void k1(const float* __restrict__ x,
                                             const float* __restrict__ mask,
                                             const float* __restrict__ w1,
                                             const float* __restrict__ bg1,
                                             const float* __restrict__ bb1,
                                             const float* __restrict__ bm1,
                                             const float* __restrict__ bv1) {
    __shared__ __align__(16) float ws[1024];  // [ic][8]

    const int t = threadIdx.x, blk = blockIdx.x;
    const int qc = blk & 3;
    const int gb = blk >> 2;
    const int g = gb / 112, pb = gb % 112;
    const int nact = g_acnt[g];
    if (pb * 7 >= nact) return;

    for (int e = t; e < 1024; e += 224) {
        int j = e >> 7, ic = e & 127;
        ws[ic * 8 + j] = w1[(g * 32 + qc * 8 + j) * 128 + ic];
    }
    __syncthreads();

    const int w = t >> 5, l = t & 31;
    const int idx = pb * 7 + w;
    if (idx >= nact) return;
    const int packed = g_lista[g * 784 + idx];
    const int pc = packed % 7;
    const int pr = (packed / 7) % 7;
    const int b = packed / 196;
    const float m = mask[packed];

    const int r = l >> 2, cp = l & 3;
    const int grow = pr * 8 + r;
    const int col = pc * 8 + cp * 2;

    const float* xp = x + (size_t)(b * 512 + g * 128) * HW + grow * 56 + col;
    float* op = g_mid1 + (size_t)(b * 128 + g * 32 + qc * 8) * HW + grow * 56 + col;

    unsigned long long A0[4], A1[4];
#pragma unroll
    for (int j = 0; j < 4; j++) { A0[j] = 0ull; A1[j] = 0ull; }

    for (int ic0 = 0; ic0 < 128; ic0 += 8) {
        float2 xv[8];
#pragma unroll
        for (int u = 0; u < 8; u++)
            xv[u] = *(const float2*)(xp + (size_t)(ic0 + u) * HW);
#pragma unroll
        for (int u = 0; u < 8; u++) {
            const ulonglong2* wp = (const ulonglong2*)(ws + (ic0 + u) * 8);
            ulonglong2 q0 = wp[0];  // oc pairs 0,1
            ulonglong2 q1 = wp[1];  // oc pairs 2,3
            unsigned long long xx0 = pk2(xv[u].x, xv[u].x);
            unsigned long long xx1 = pk2(xv[u].y, xv[u].y);
            fma2(A0[0], xx0, q0.x); fma2(A0[1], xx0, q0.y);
            fma2(A0[2], xx0, q1.x); fma2(A0[3], xx0, q1.y);
            fma2(A1[0], xx1, q0.x); fma2(A1[1], xx1, q0.y);
            fma2(A1[2], xx1, q1.x); fma2(A1[3], xx1, q1.y);
        }
    }
#pragma unroll
    for (int p = 0; p < 4; p++) {
        float2 u0 = upk2(A0[p]);
        float2 u1 = upk2(A1[p]);
        float a0[2] = {u0.x, u0.y}, a1[2] = {u1.x, u1.y};
#pragma unroll
        for (int jj = 0; jj < 2; jj++) {
            int j = p * 2 + jj;
            int c = g * 32 + qc * 8 + j;
            float s = bg1[c] * rsqrtf(bv1[c] + EPS);
            float bb = bb1[c] - bm1[c] * s;
            float v0 = fmaxf(fmaf(m * a0[jj], s, bb), 0.f) * m;
            float v1 = fmaxf(fmaf(m * a1[jj], s, bb), 0.f) * m;
            *(float2*)(op + (size_t)j * HW) = make_float2(v0, v1);
        }
    }
}

// ---------------------------------------------------------------------------
// K2: 3x3 conv (32 -> 8 oc per block, pad 1) + BN2 + ReLU + mask
// grid = 4 qc * 4 g * 112 pb; active patches of one group only
// smem weight layout: [ic][tap k][8 oc]
// ---------------------------------------------------------------------------
__global__ __launch_bounds__(224, 4) void k2(const float* __restrict__ mask,
                                             const float* __restrict__ w2,
                                             const float* __restrict__ bg2,
                                             const float* __restrict__ bb2,
                                             const float* __restrict__ bm2,
                                             const float* __restrict__ bv2) {
    __shared__ __align__(16) float ws[2304];  // [ic][9][8]

    const int t = threadIdx.x, blk = blockIdx.x;
    const int qc = blk & 3;
    const int gb = blk >> 2;
    const int g = gb / 112, pb = gb % 112;
    const int nact = g_acnt[g];
    if (pb * 7 >= nact) return;

    for (int e = t; e < 2304; e += 224) {
        int j = e / 288;
        int rem = e - j * 288;
        int ic = rem / 9;
        int k = rem - ic * 9;
        ws[(ic * 9 + k) * 8 + j] = w2[((g * 32 + qc * 8 + j) * 32 + ic) * 9 + k];
    }
    __syncthreads();

    const int w = t >> 5, l = t & 31;
    const int idx = pb * 7 + w;
    if (idx >= nact) return;
    const int packed = g_lista[g * 784 + idx];
    const int pc = packed % 7;
    const int pr = (packed / 7) % 7;
    const int b = packed / 196;
    const float m = mask[packed];

    const int r = l >> 2, cp = l & 3;
    const int grow = pr * 8 + r;
    const int col = pc * 8 + cp * 2;

    float* op = g_mid2 + (size_t)(b * 128 + g * 32 + qc * 8) * HW + grow * 56 + col;
    const float* mb = g_mid1 + (size_t)(b * 128 + g * 32) * HW + col;

    unsigned long long A0[4], A1[4];
#pragma unroll
    for (int j = 0; j < 4; j++) { A0[j] = 0ull; A1[j] = 0ull; }

#pragma unroll 2
    for (int ic = 0; ic < 32; ic++) {
        const float* pic = mb + (size_t)ic * HW;
        float xm[3], x2[3];
        float2 xc[3];
#pragma unroll
        for (int dy = 0; dy < 3; dy++) {
            int yy = grow - 1 + dy;
            bool v = (yy >= 0) && (yy < 56);
            const float* p = pic + yy * 56;
            xm[dy] = (v && col > 0) ? p[-1] : 0.f;
            xc[dy] = v ? *(const float2*)p : make_float2(0.f, 0.f);
            x2[dy] = (v && col < 54) ? p[2] : 0.f;
        }
#pragma unroll
        for (int dy = 0; dy < 3; dy++) {
            const ulonglong2* wp = (const ulonglong2*)(ws + (ic * 9 + dy * 3) * 8);
            ulonglong2 ta = wp[0];   // tap dx=0, oc pairs 0,1
            ulonglong2 tA = wp[1];   // tap dx=0, oc pairs 2,3
            ulonglong2 tb = wp[2];   // tap dx=1, oc pairs 0,1
            ulonglong2 tB = wp[3];   // tap dx=1, oc pairs 2,3
            ulonglong2 tc = wp[4];   // tap dx=2, oc pairs 0,1
            ulonglong2 tC = wp[5];   // tap dx=2, oc pairs 2,3
            unsigned long long t00 = pk2(xm[dy], xm[dy]);
            unsigned long long t11 = pk2(xc[dy].x, xc[dy].x);
            unsigned long long t22 = pk2(xc[dy].y, xc[dy].y);
            unsigned long long t33 = pk2(x2[dy], x2[dy]);
            fma2(A0[0], t00, ta.x); fma2(A0[1], t00, ta.y);
            fma2(A0[2], t00, tA.x); fma2(A0[3], t00, tA.y);
            fma2(A0[0], t11, tb.x); fma2(A0[1], t11, tb.y);
            fma2(A0[2], t11, tB.x); fma2(A0[3], t11, tB.y);
            fma2(A0[0], t22, tc.x); fma2(A0[1], t22, tc.y);
            fma2(A0[2], t22, tC.x); fma2(A0[3], t22, tC.y);
            fma2(A1[0], t11, ta.x); fma2(A1[1], t11, ta.y);
            fma2(A1[2], t11, tA.x); fma2(A1[3], t11, tA.y);
            fma2(A1[0], t22, tb.x); fma2(A1[1], t22, tb.y);
            fma2(A1[2], t22, tB.x); fma2(A1[3], t22, tB.y);
            fma2(A1[0], t33, tc.x); fma2(A1[1], t33, tc.y);
            fma2(A1[2], t33, tC.x); fma2(A1[3], t33, tC.y);
        }
    }
#pragma unroll
    for (int p = 0; p < 4; p++) {
        float2 u0 = upk2(A0[p]);
        float2 u1 = upk2(A1[p]);
        float a0[2] = {u0.x, u0.y}, a1[2] = {u1.x, u1.y};
#pragma unroll
        for (int jj = 0; jj < 2; jj++) {
            int j = p * 2 + jj;
            int c = g * 32 + qc * 8 + j;
            float s = bg2[c] * rsqrtf(bv2[c] + EPS);
            float bb = bb2[c] - bm2[c] * s;
            float v0 = fmaxf(fmaf(a0[jj], s, bb), 0.f) * m;
            float v1 = fmaxf(fmaf(a1[jj], s, bb), 0.f) * m;
            *(float2*)(op + (size_t)j * HW) = make_float2(v0, v1);
        }
    }
}

// ---------------------------------------------------------------------------
// K3: 1x1 conv (32 -> 8 oc per block) + BN3 + residual + ReLU (all patches)
// grid = (b, g, pr, qc in 0..15)  -- memory-bound; unchanged from R9
// ---------------------------------------------------------------------------
__global__ __launch_bounds__(224, 5) void k3(const float* __restrict__ x,
                                             const float* __restrict__ mask,
                                             const float* __restrict__ w3,
                                             const float* __restrict__ bg3,
                                             const float* __restrict__ bb3,
                                             const float* __restrict__ bm3,
                                             const float* __restrict__ bv3,
                                             float* __restrict__ out) {
    __shared__ __align__(16) float ws[256];  // [ic][8]

    const int t = threadIdx.x, blk = blockIdx.x;
    const int qc = blk & 15;
    const int rest = blk >> 4;
    const int pr = rest % 7;
    const int bg = rest / 7;
    const int g = bg & 3, b = bg >> 2;

    for (int e = t; e < 256; e += 224) {
        int j = e >> 5, ic = e & 31;
        ws[ic * 8 + j] = w3[(g * 128 + qc * 8 + j) * 32 + ic];
    }
    __syncthreads();

    const int w = t >> 5, l = t & 31;
    const int r = l >> 2, cp = l & 3;
    const int grow = pr * 8 + r;
    const int col = w * 8 + cp * 2;
    const float m = mask[((b * 4 + g) * 7 + pr) * 7 + w];

    const float* resp = x + (size_t)(b * 512 + g * 128 + qc * 8) * HW + grow * 56 + col;
    float* op = out + (size_t)(b * 512 + g * 128 + qc * 8) * HW + grow * 56 + col;

    float sc[8], bi[8];
#pragma unroll
    for (int j = 0; j < 8; j++) {
        int c = g * 128 + qc * 8 + j;
        float s = bg3[c] * rsqrtf(bv3[c] + EPS);
        sc[j] = s;
        bi[j] = bb3[c] - bm3[c] * s;
    }

    if (m != 0.f) {
        const float* mp = g_mid2 + (size_t)(b * 128 + g * 32) * HW + grow * 56 + col;
        unsigned long long A0[4], A1[4];
#pragma unroll
        for (int j = 0; j < 4; j++) { A0[j] = 0ull; A1[j] = 0ull; }

        for (int ic0 = 0; ic0 < 32; ic0 += 8) {
            float2 xv[8];
#pragma unroll
            for (int u = 0; u < 8; u++)
                xv[u] = *(const float2*)(mp + (size_t)(ic0 + u) * HW);
#pragma unroll
            for (int u = 0; u < 8; u++) {
                const ulonglong2* wp = (const ulonglong2*)(ws + (ic0 + u) * 8);
                ulonglong2 q0 = wp[0];
                ulonglong2 q1 = wp[1];
                unsigned long long xx0 = pk2(xv[u].x, xv[u].x);
                unsigned long long xx1 = pk2(xv[u].y, xv[u].y);
                fma2(A0[0], xx0, q0.x); fma2(A0[1], xx0, q0.y);
                fma2(A0[2], xx0, q1.x); fma2(A0[3], xx0, q1.y);
                fma2(A1[0], xx1, q0.x); fma2(A1[1], xx1, q0.y);
                fma2(A1[2], xx1, q1.x); fma2(A1[3], xx1, q1.y);
            }
        }
#pragma unroll
        for (int p = 0; p < 4; p++) {
            float2 u0 = upk2(A0[p]);
            float2 u1 = upk2(A1[p]);
            float a0[2] = {u0.x, u0.y}, a1[2] = {u1.x, u1.y};
#pragma unroll
            for (int jj = 0; jj < 2; jj++) {
                int j = p * 2 + jj;
                float2 res = *(const float2*)(resp + (size_t)j * HW);
                float v0 = fmaxf(fmaf(a0[jj], sc[j], bi[j]) + res.x, 0.f);
                float v1 = fmaxf(fmaf(a1[jj], sc[j], bi[j]) + res.y, 0.f);
                *(float2*)(op + (size_t)j * HW) = make_float2(v0, v1);
            }
        }
    } else {
#pragma unroll
        for (int j = 0; j < 8; j++) {
            float2 res = *(const float2*)(resp + (size_t)j * HW);
            float v0 = fmaxf(bi[j] + res.x, 0.f);
            float v1 = fmaxf(bi[j] + res.y, 0.f);
            *(float2*)(op + (size_t)j * HW) = make_float2(v0, v1);
        }
    }
}

// ---------------------------------------------------------------------------
extern "C" void kernel_launch(void* const* d_in, const int* in_sizes, int n_in,
                              void* d_out, int out_size) {
    const float* x    = (const float*)d_in[0];
    const float* mask = (const float*)d_in[1];
    const float* w1   = (const float*)d_in[2];
    const float* g1 = (const float*)d_in[3];
    const float* b1 = (const float*)d_in[4];
    const float* m1 = (const float*)d_in[5];
    const float* v1 = (const float*)d_in[6];
    const float* w2   = (const float*)d_in[7];
    const float* g2 = (const float*)d_in[8];
    const float* b2 = (const float*)d_in[9];
    const float* m2 = (const float*)d_in[10];
    const float* v2 = (const float*)d_in[11];
    const float* w3   = (const float*)d_in[12];
    const float* g3 = (const float*)d_in[13];
    const float* b3 = (const float*)d_in[14];
    const float* m3 = (const float*)d_in[15];
    const float* v3 = (const float*)d_in[16];
    float* out = (float*)d_out;

    prep<<<1, 1024>>>(mask);
    zero_inactive<<<448, 224>>>();

    k1<<<4 * 4 * 112, 224>>>(x, mask, w1, g1, b1, m1, v1);
    k2<<<4 * 4 * 112, 224>>>(mask, w2, g2, b2, m2, v2);
    k3<<<16 * 4 * 7 * 16, 224>>>(x, mask, w3, g3, b3, m3, v3, out);
}